// round 13
// baseline (speedup 1.0000x reference)
#include <cuda_runtime.h>
#include <cstdint>

#define K_DIM   2048
#define N_EXP   64
#define TM      128
#define TK      64
#define NKT     32
#define THREADS 1024
#define ASTRIDE 72
#define ASTAGE  (TM * ASTRIDE)
#define BWORDS  4096
#define LDL     72
#define TOPK_TEMP 2.0f
#define SMEM_BYTES (3 * ASTAGE * 4 + 3 * BWORDS * 4)   // 159744

__device__ uint32_t g_wfrag[NKT * BWORDS];

__device__ __forceinline__ uint32_t pack2(float f0, float f1) {
    uint32_t r;
    asm("cvt.rn.bf16x2.f32 %0, %1, %2;" : "=r"(r) : "f"(f1), "f"(f0));
    return r;
}
__device__ __forceinline__ void split2(float f0, float f1, uint32_t &h, uint32_t &l) {
    h = pack2(f0, f1);
    float h0 = __uint_as_float(h << 16);
    float h1 = __uint_as_float(h & 0xFFFF0000u);
    l = pack2(f0 - h0, f1 - h1);
}
__device__ __forceinline__ void mma16816(float *d,
                                         uint32_t a0, uint32_t a1, uint32_t a2, uint32_t a3,
                                         uint32_t b0, uint32_t b1) {
    asm volatile("mma.sync.aligned.m16n8k16.row.col.f32.bf16.bf16.f32 "
                 "{%0,%1,%2,%3}, {%4,%5,%6,%7}, {%8,%9}, {%0,%1,%2,%3};"
                 : "+f"(d[0]), "+f"(d[1]), "+f"(d[2]), "+f"(d[3])
                 : "r"(a0), "r"(a1), "r"(a2), "r"(a3), "r"(b0), "r"(b1));
}
__device__ __forceinline__ void cp16(uint32_t dst, const void* src) {
    asm volatile("cp.async.cg.shared.global [%0], [%1], 16;" :: "r"(dst), "l"(src));
}

__global__ __launch_bounds__(256)
void dhr_wprep_kernel(const float* __restrict__ w)
{
    const int kt = blockIdx.x;
    const int t  = threadIdx.x;
    const int bp  = t & 31;
    const int bks = bp >> 3;
    const int brg = (bp >> 2) & 1;
    const int bn0 = t >> 5;
    const int bln = (bn0 << 2) | (bp & 3);
    const float* pW = w + bn0 * K_DIM + kt * TK + 2 * bp;
    uint32_t* dst0 = g_wfrag + kt * BWORDS;
    #pragma unroll
    for (int i = 0; i < 8; i++) {
        float2 wv = *(const float2*)(pW + i * 8 * K_DIM);
        uint32_t h, l; split2(wv.x, wv.y, h, l);
        uint32_t* d = dst0 + (((bks * 8 + i) * 32 + bln) << 2);
        d[brg] = h; d[2 + brg] = l;
    }
}

__global__ __launch_bounds__(THREADS, 1)
void dhr_wide_kernel(const float* __restrict__ x,
                     const float* __restrict__ bias,
                     const int*   __restrict__ mat,
                     float* __restrict__ out)
{
    extern __shared__ __align__(16) float smem[];
    uint32_t* Bbase = (uint32_t*)(smem + 3 * ASTAGE);

    const int t    = threadIdx.x;
    const int wid  = t >> 5;               // 0..31
    const int lane = t & 31;
    const int q    = lane & 3;
    const int g    = lane >> 2;
    const int kh     = wid & 1;            // k-half
    const int stripe = (wid >> 1) & 7;     // m-tile 0..7
    const int nH     = wid >> 4;           // n-half
    const int mrow   = stripe * 16;
    const long rowBase = (long)blockIdx.x * TM;

    const uint32_t aSmem = (uint32_t)__cvta_generic_to_shared(smem);
    const uint32_t bSmem = (uint32_t)__cvta_generic_to_shared(Bbase);

    float acc[4][4];
    #pragma unroll
    for (int j = 0; j < 4; j++)
        acc[j][0] = acc[j][1] = acc[j][2] = acc[j][3] = 0.f;

    // ---- prologue: stages 0,1 ----
    #pragma unroll
    for (int s0 = 0; s0 < 2; s0++) {
        #pragma unroll
        for (int ss = 0; ss < 2; ss++) {
            int idx = ss * THREADS + t;        // 0..2047
            int r = idx >> 4, cc = idx & 15;
            cp16(aSmem + (s0 * ASTAGE + r * ASTRIDE) * 4 + cc * 16,
                 x + (rowBase + r) * K_DIM + s0 * TK + cc * 4);
        }
        cp16(bSmem + s0 * BWORDS * 4 + t * 16,
             g_wfrag + s0 * BWORDS + t * 4);
        asm volatile("cp.async.commit_group;");
    }

    // ---- mainloop ----
    for (int kt = 0; kt < NKT; kt++) {
        asm volatile("cp.async.wait_group %0;" :: "n"(1));
        __syncthreads();

        if (kt + 2 < NKT) {
            int s = (kt + 2) % 3;
            #pragma unroll
            for (int ss = 0; ss < 2; ss++) {
                int idx = ss * THREADS + t;
                int r = idx >> 4, cc = idx & 15;
                cp16(aSmem + (s * ASTAGE + r * ASTRIDE) * 4 + cc * 16,
                     x + (rowBase + r) * K_DIM + (kt + 2) * TK + cc * 4);
            }
            cp16(bSmem + s * BWORDS * 4 + t * 16,
                 g_wfrag + (kt + 2) * BWORDS + t * 4);
        }
        asm volatile("cp.async.commit_group;");

        const float*    As = smem + (kt % 3) * ASTAGE;
        const uint32_t* Bs = Bbase + (kt % 3) * BWORDS;

        #pragma unroll
        for (int kk = 0; kk < 2; kk++) {
            const int ks = kh * 2 + kk;
            const float* p = As + (mrow + g) * ASTRIDE + ks * 16 + 2 * q;
            float2 v0 = *(const float2*)(p);
            float2 v1 = *(const float2*)(p + 8 * ASTRIDE);
            float2 v2 = *(const float2*)(p + 8);
            float2 v3 = *(const float2*)(p + 8 * ASTRIDE + 8);
            uint32_t ah[4], al[4];
            split2(v0.x, v0.y, ah[0], al[0]);
            split2(v1.x, v1.y, ah[1], al[1]);
            split2(v2.x, v2.y, ah[2], al[2]);
            split2(v3.x, v3.y, ah[3], al[3]);
            #pragma unroll
            for (int j = 0; j < 4; j++) {
                int tt = nH * 4 + j;
                uint4 bf = *(const uint4*)(Bs + (((ks * 8 + tt) * 32 + lane) << 2));
                mma16816(acc[j], ah[0], ah[1], ah[2], ah[3], bf.x, bf.y);
                mma16816(acc[j], ah[0], ah[1], ah[2], ah[3], bf.z, bf.w);
                mma16816(acc[j], al[0], al[1], al[2], al[3], bf.x, bf.y);
            }
        }
    }
    __syncthreads();

    // ---- epilogue: combine kh halves + bias into SMEM logits ----
    float* L = smem;
    if (kh == 0) {
        #pragma unroll
        for (int j = 0; j < 4; j++) {
            int c = (nH * 4 + j) * 8 + 2 * q;
            float b0 = __ldg(&bias[c]);
            float b1 = __ldg(&bias[c + 1]);
            int r0 = mrow + g;
            L[r0 * LDL + c]           = acc[j][0] + b0;
            L[r0 * LDL + c + 1]       = acc[j][1] + b1;
            L[(r0 + 8) * LDL + c]     = acc[j][2] + b0;
            L[(r0 + 8) * LDL + c + 1] = acc[j][3] + b1;
        }
    }
    __syncthreads();
    if (kh == 1) {
        #pragma unroll
        for (int j = 0; j < 4; j++) {
            int c = (nH * 4 + j) * 8 + 2 * q;
            int r0 = mrow + g;
            L[r0 * LDL + c]           += acc[j][0];
            L[r0 * LDL + c + 1]       += acc[j][1];
            L[(r0 + 8) * LDL + c]     += acc[j][2];
            L[(r0 + 8) * LDL + c + 1] += acc[j][3];
        }
    }
    __syncthreads();

    // ---- routing: one thread per row ----
    if (t < TM) {
        bool any_immature = false;
        #pragma unroll 8
        for (int e = 0; e < N_EXP; e++)
            any_immature |= (__ldg(&mat[e]) == 0);

        float* row = &L[t * LDL];
        if (!any_immature) {
            float v1 = -__int_as_float(0x7f800000), v2 = v1;
            int i1 = 0, i2 = 0;
            #pragma unroll 8
            for (int e = 0; e < N_EXP; e++) {
                float v = row[e];
                if (v > v1)      { v2 = v1; i2 = i1; v1 = v; i1 = e; }
                else if (v > v2) { v2 = v;  i2 = e; }
            }
            float e2  = __expf(v2 - v1);
            float inv = 1.0f / (1.0f + e2);
            #pragma unroll 8
            for (int e = 0; e < N_EXP; e++) row[e] = 0.0f;
            row[i1] = inv;
            row[i2] = e2 * inv;
        } else {
            float m = -__int_as_float(0x7f800000);
            #pragma unroll 8
            for (int e = 0; e < N_EXP; e++) m = fmaxf(m, row[e]);
            float s = 0.0f;
            float tmp[N_EXP];
            #pragma unroll 8
            for (int e = 0; e < N_EXP; e++) {
                float v = __expf((row[e] - m) * (1.0f / TOPK_TEMP));
                tmp[e] = v; s += v;
            }
            float invs = 1.0f / s;
            #pragma unroll 8
            for (int e = 0; e < N_EXP; e++) row[e] = tmp[e] * invs;
        }
    }
    __syncthreads();

    // ---- coalesced float4 store of 128x64 tile ----
    #pragma unroll
    for (int s = 0; s < (TM * N_EXP / 4) / THREADS; s++) {   // 2
        int idx = s * THREADS + t;
        int r = idx >> 4;
        int c = (idx & 15) << 2;
        float4 v = *(const float4*)&L[r * LDL + c];
        *(float4*)(out + (rowBase + r) * N_EXP + c) = v;
    }
}

extern "C" void kernel_launch(void* const* d_in, const int* in_sizes, int n_in,
                              void* d_out, int out_size)
{
    const float* x   = (const float*)d_in[0];   // [16384, 2048]
    const float* w   = (const float*)d_in[1];   // [64, 2048]
    const float* b   = (const float*)d_in[2];   // [64]
    const int*   mat = (const int*)  d_in[3];   // [64]
    float* out = (float*)d_out;                 // [16384, 64]

    cudaFuncSetAttribute(dhr_wide_kernel,
                         cudaFuncAttributeMaxDynamicSharedMemorySize, SMEM_BYTES);

    dhr_wprep_kernel<<<NKT, 256>>>(w);

    int rows = in_sizes[0] / K_DIM;             // 16384
    int grid = rows / TM;                       // 128
    dhr_wide_kernel<<<grid, THREADS, SMEM_BYTES>>>(x, b, mat, out);
}

// round 14
// speedup vs baseline: 1.1185x; 1.1185x over previous
#include <cuda_runtime.h>
#include <cstdint>

#define K_DIM   2048
#define N_EXP   64
#define TMX     112                 // rows per CTA (7 m-tiles)
#define TK      64
#define NKT     32
#define THREADS 512
#define ASTRIDE 72
#define ASTG    (TMX * ASTRIDE)     // 8064 floats per A stage
#define ACH     (TMX * 16)          // 1792 16B chunks per A stage
#define BWORDS  4096                // uint32 per B stage
#define LDL     72
#define TOPK_TEMP 2.0f
#define SMEM_BYTES (4 * ASTG * 4 + 4 * BWORDS * 4)   // 194560

__device__ uint32_t g_wfrag[NKT * BWORDS];

__device__ __forceinline__ uint32_t pack2(float f0, float f1) {
    uint32_t r;
    asm("cvt.rn.bf16x2.f32 %0, %1, %2;" : "=r"(r) : "f"(f1), "f"(f0));
    return r;
}
__device__ __forceinline__ void split2(float f0, float f1, uint32_t &h, uint32_t &l) {
    h = pack2(f0, f1);
    float h0 = __uint_as_float(h << 16);
    float h1 = __uint_as_float(h & 0xFFFF0000u);
    l = pack2(f0 - h0, f1 - h1);
}
__device__ __forceinline__ void mma16816(float *d,
                                         uint32_t a0, uint32_t a1, uint32_t a2, uint32_t a3,
                                         uint32_t b0, uint32_t b1) {
    asm volatile("mma.sync.aligned.m16n8k16.row.col.f32.bf16.bf16.f32 "
                 "{%0,%1,%2,%3}, {%4,%5,%6,%7}, {%8,%9}, {%0,%1,%2,%3};"
                 : "+f"(d[0]), "+f"(d[1]), "+f"(d[2]), "+f"(d[3])
                 : "r"(a0), "r"(a1), "r"(a2), "r"(a3), "r"(b0), "r"(b1));
}
__device__ __forceinline__ void cp16(uint32_t dst, const void* src) {
    asm volatile("cp.async.cg.shared.global [%0], [%1], 16;" :: "r"(dst), "l"(src));
}

__global__ __launch_bounds__(256)
void dhr_wprep_kernel(const float* __restrict__ w)
{
    const int kt = blockIdx.x;
    const int t  = threadIdx.x;
    const int bp  = t & 31;
    const int bks = bp >> 3;
    const int brg = (bp >> 2) & 1;
    const int bn0 = t >> 5;
    const int bln = (bn0 << 2) | (bp & 3);
    const float* pW = w + bn0 * K_DIM + kt * TK + 2 * bp;
    uint32_t* dst0 = g_wfrag + kt * BWORDS;
    #pragma unroll
    for (int i = 0; i < 8; i++) {
        float2 wv = *(const float2*)(pW + i * 8 * K_DIM);
        uint32_t h, l; split2(wv.x, wv.y, h, l);
        uint32_t* d = dst0 + (((bks * 8 + i) * 32 + bln) << 2);
        d[brg] = h; d[2 + brg] = l;
    }
}

// load one A tile (col k0) + one B tile into stage (compile-time constant sidx)
__device__ __forceinline__ void stage_in(int sidx, int k0, long rowBase, long rowMax,
                                         const float* __restrict__ x,
                                         uint32_t aSmem, uint32_t bSmem, int t)
{
    #pragma unroll
    for (int ss = 0; ss < 4; ss++) {
        int idx = ss * THREADS + t;
        if (idx < ACH) {
            int r = idx >> 4, cc = idx & 15;
            long rg = rowBase + r; if (rg > rowMax) rg = rowMax;
            cp16(aSmem + (sidx * ASTG + r * ASTRIDE) * 4 + cc * 16,
                 x + rg * K_DIM + k0 + cc * 4);
        }
    }
    #pragma unroll
    for (int ss = 0; ss < 2; ss++) {
        int idx = ss * THREADS + t;
        cp16(bSmem + (sidx * BWORDS + idx * 4) * 4,
             g_wfrag + (k0 >> 6) * BWORDS + idx * 4);
    }
}

__global__ __launch_bounds__(THREADS, 1)
void dhr_u112_kernel(const float* __restrict__ x,
                     const float* __restrict__ bias,
                     const int*   __restrict__ mat,
                     float* __restrict__ out, long rowsTotal)
{
    extern __shared__ __align__(16) float smem[];
    uint32_t* Bbase = (uint32_t*)(smem + 4 * ASTG);

    const int t    = threadIdx.x;
    const int wid  = t >> 5;
    const int lane = t & 31;
    const int q    = lane & 3;
    const int g    = lane >> 2;
    const int kh   = wid & 1;              // k-half
    const int nH   = (wid >> 1) & 1;       // n-half
    const int ws   = wid >> 2;             // 0..3 -> m-tiles {ws, ws+4}
    const int two  = (ws < 3);             // ws=3 owns only m-tile 3
    const long rowBase = (long)blockIdx.x * TMX;
    const long rowMax  = rowsTotal - 1;

    const uint32_t aSmem = (uint32_t)__cvta_generic_to_shared(smem);
    const uint32_t bSmem = (uint32_t)__cvta_generic_to_shared(Bbase);

    float acc[2][4][4];
    #pragma unroll
    for (int m = 0; m < 2; m++)
        #pragma unroll
        for (int j = 0; j < 4; j++)
            acc[m][j][0] = acc[m][j][1] = acc[m][j][2] = acc[m][j][3] = 0.f;

    // ---- prologue: tiles 0,1 into stages 0,1 ----
    stage_in(0, 0,  rowBase, rowMax, x, aSmem, bSmem, t);
    asm volatile("cp.async.commit_group;");
    stage_in(1, TK, rowBase, rowMax, x, aSmem, bSmem, t);
    asm volatile("cp.async.commit_group;");

    // ---- mainloop: 8 outer x 4 unrolled, stage = ki (compile-time) ----
    for (int kto = 0; kto < 8; kto++) {
        #pragma unroll
        for (int ki = 0; ki < 4; ki++) {
            const int kt = kto * 4 + ki;
            asm volatile("cp.async.wait_group %0;" :: "n"(1));
            __syncthreads();

            if (kto < 7 || ki < 2) {
                stage_in((ki + 2) & 3, (kt + 2) * TK, rowBase, rowMax, x, aSmem, bSmem, t);
            }
            asm volatile("cp.async.commit_group;");

            const float*    As = smem + ki * ASTG;
            const uint32_t* Bs = Bbase + ki * BWORDS;

            #pragma unroll
            for (int kk = 0; kk < 2; kk++) {
                const int ks = kh * 2 + kk;
                uint32_t ah[2][4], al[2][4];
                {   // m-tile ws
                    const float* pm = As + (ws * 16 + g) * ASTRIDE + ks * 16 + 2 * q;
                    float2 v0 = *(const float2*)(pm);
                    float2 v1 = *(const float2*)(pm + 8 * ASTRIDE);
                    float2 v2 = *(const float2*)(pm + 8);
                    float2 v3 = *(const float2*)(pm + 8 * ASTRIDE + 8);
                    split2(v0.x, v0.y, ah[0][0], al[0][0]);
                    split2(v1.x, v1.y, ah[0][1], al[0][1]);
                    split2(v2.x, v2.y, ah[0][2], al[0][2]);
                    split2(v3.x, v3.y, ah[0][3], al[0][3]);
                }
                if (two) {   // m-tile ws+4
                    const float* pm = As + ((ws + 4) * 16 + g) * ASTRIDE + ks * 16 + 2 * q;
                    float2 v0 = *(const float2*)(pm);
                    float2 v1 = *(const float2*)(pm + 8 * ASTRIDE);
                    float2 v2 = *(const float2*)(pm + 8);
                    float2 v3 = *(const float2*)(pm + 8 * ASTRIDE + 8);
                    split2(v0.x, v0.y, ah[1][0], al[1][0]);
                    split2(v1.x, v1.y, ah[1][1], al[1][1]);
                    split2(v2.x, v2.y, ah[1][2], al[1][2]);
                    split2(v3.x, v3.y, ah[1][3], al[1][3]);
                }
                #pragma unroll
                for (int j = 0; j < 4; j++) {
                    int tt = nH * 4 + j;
                    uint4 bf = *(const uint4*)(Bs + (((ks * 8 + tt) * 32 + lane) << 2));
                    mma16816(acc[0][j], ah[0][0], ah[0][1], ah[0][2], ah[0][3], bf.x, bf.y);
                    mma16816(acc[0][j], ah[0][0], ah[0][1], ah[0][2], ah[0][3], bf.z, bf.w);
                    mma16816(acc[0][j], al[0][0], al[0][1], al[0][2], al[0][3], bf.x, bf.y);
                    if (two) {
                        mma16816(acc[1][j], ah[1][0], ah[1][1], ah[1][2], ah[1][3], bf.x, bf.y);
                        mma16816(acc[1][j], ah[1][0], ah[1][1], ah[1][2], ah[1][3], bf.z, bf.w);
                        mma16816(acc[1][j], al[1][0], al[1][1], al[1][2], al[1][3], bf.x, bf.y);
                    }
                }
            }
        }
    }
    __syncthreads();

    // ---- epilogue: combine kh halves + bias into SMEM logits ----
    float* L = smem;
    if (kh == 0) {
        #pragma unroll
        for (int m = 0; m < 2; m++) {
            if (m == 0 || two) {
                #pragma unroll
                for (int j = 0; j < 4; j++) {
                    int c = (nH * 4 + j) * 8 + 2 * q;
                    float b0 = __ldg(&bias[c]);
                    float b1 = __ldg(&bias[c + 1]);
                    int r0 = (ws + 4 * m) * 16 + g;
                    L[r0 * LDL + c]           = acc[m][j][0] + b0;
                    L[r0 * LDL + c + 1]       = acc[m][j][1] + b1;
                    L[(r0 + 8) * LDL + c]     = acc[m][j][2] + b0;
                    L[(r0 + 8) * LDL + c + 1] = acc[m][j][3] + b1;
                }
            }
        }
    }
    __syncthreads();
    if (kh == 1) {
        #pragma unroll
        for (int m = 0; m < 2; m++) {
            if (m == 0 || two) {
                #pragma unroll
                for (int j = 0; j < 4; j++) {
                    int c = (nH * 4 + j) * 8 + 2 * q;
                    int r0 = (ws + 4 * m) * 16 + g;
                    L[r0 * LDL + c]           += acc[m][j][0];
                    L[r0 * LDL + c + 1]       += acc[m][j][1];
                    L[(r0 + 8) * LDL + c]     += acc[m][j][2];
                    L[(r0 + 8) * LDL + c + 1] += acc[m][j][3];
                }
            }
        }
    }
    __syncthreads();

    // ---- routing: one thread per row ----
    if (t < TMX) {
        bool any_immature = false;
        #pragma unroll 8
        for (int e = 0; e < N_EXP; e++)
            any_immature |= (__ldg(&mat[e]) == 0);

        float* row = &L[t * LDL];
        if (!any_immature) {
            float v1 = -__int_as_float(0x7f800000), v2 = v1;
            int i1 = 0, i2 = 0;
            #pragma unroll 8
            for (int e = 0; e < N_EXP; e++) {
                float v = row[e];
                if (v > v1)      { v2 = v1; i2 = i1; v1 = v; i1 = e; }
                else if (v > v2) { v2 = v;  i2 = e; }
            }
            float e2  = __expf(v2 - v1);
            float inv = 1.0f / (1.0f + e2);
            #pragma unroll 8
            for (int e = 0; e < N_EXP; e++) row[e] = 0.0f;
            row[i1] = inv;
            row[i2] = e2 * inv;
        } else {
            float m = -__int_as_float(0x7f800000);
            #pragma unroll 8
            for (int e = 0; e < N_EXP; e++) m = fmaxf(m, row[e]);
            float s = 0.0f;
            float tmp[N_EXP];
            #pragma unroll 8
            for (int e = 0; e < N_EXP; e++) {
                float v = __expf((row[e] - m) * (1.0f / TOPK_TEMP));
                tmp[e] = v; s += v;
            }
            float invs = 1.0f / s;
            #pragma unroll 8
            for (int e = 0; e < N_EXP; e++) row[e] = tmp[e] * invs;
        }
    }
    __syncthreads();

    // ---- coalesced float4 store (guard rows beyond rowsTotal) ----
    #pragma unroll
    for (int ss = 0; ss < 4; ss++) {
        int idx = ss * THREADS + t;          // 0..2047 > 1792 guarded
        if (idx < TMX * 16) {
            int r = idx >> 4;
            int c = (idx & 15) << 2;
            if (rowBase + r < rowsTotal) {
                float4 v = *(const float4*)&L[r * LDL + c];
                *(float4*)(out + (rowBase + r) * N_EXP + c) = v;
            }
        }
    }
}

extern "C" void kernel_launch(void* const* d_in, const int* in_sizes, int n_in,
                              void* d_out, int out_size)
{
    const float* x   = (const float*)d_in[0];   // [16384, 2048]
    const float* w   = (const float*)d_in[1];   // [64, 2048]
    const float* b   = (const float*)d_in[2];   // [64]
    const int*   mat = (const int*)  d_in[3];   // [64]
    float* out = (float*)d_out;                 // [16384, 64]

    const long ROWS = in_sizes[0] / K_DIM;      // 16384
    const int  grid = (int)((ROWS + TMX - 1) / TMX);   // 147

    cudaFuncSetAttribute(dhr_u112_kernel,
                         cudaFuncAttributeMaxDynamicSharedMemorySize, SMEM_BYTES);

    dhr_wprep_kernel<<<NKT, 256>>>(w);
    dhr_u112_kernel<<<grid, THREADS, SMEM_BYTES>>>(x, b, mat, out, ROWS);
}